// round 12
// baseline (speedup 1.0000x reference)
#include <cuda_runtime.h>

#define IMG   256
#define NPTS  320
#define NSEG  4
#define SEGLEN (NPTS / NSEG)

// Scratch (device globals: no allocations allowed)
__device__ float g_feat[NSEG][IMG * IMG];
__device__ float g_trans[NSEG][IMG * IMG];
__device__ float g_screen[IMG * IMG];
__device__ float g_consts[4];   // mean, 1/(std+1e-8), s_min, 1/(s_max-s_min+1e-8)

__device__ __forceinline__ void slab_axis(float Gd, float G0, float& dlo, float& dhi) {
    // contributing range of grid coord g is (-1, 256)
    if (fabsf(Gd) > 1e-12f) {
        float inv = 1.0f / Gd;
        float a = (-1.0f - G0) * inv;
        float b = (256.0f - G0) * inv;
        dlo = fmaxf(dlo, fminf(a, b));
        dhi = fminf(dhi, fmaxf(a, b));
    } else if (G0 <= -1.0f || G0 >= 256.0f) {
        dhi = -1.0f;  // empty
    }
}

__global__ void __launch_bounds__(64) render_kernel(
    const float* __restrict__ vol,
    const float* __restrict__ Rm,
    const float* __restrict__ Tv,
    const float* __restrict__ Fv)
{
    const int w   = blockIdx.x * 8 + threadIdx.x;   // image x (xs index)
    const int h   = blockIdx.y * 8 + threadIdx.y;   // image y (ys index)
    const int seg = blockIdx.z;
    const float kstep = 6.0f / 319.0f;

    const float f  = __ldg(Fv);
    const float ux = (255.0f - 2.0f * (float)w) * (1.0f / 256.0f) / f;
    const float uy = (255.0f - 2.0f * (float)h) * (1.0f / 256.0f) / f;

    const float r00 = __ldg(Rm + 0), r01 = __ldg(Rm + 1), r02 = __ldg(Rm + 2);
    const float r10 = __ldg(Rm + 3), r11 = __ldg(Rm + 4), r12 = __ldg(Rm + 5);
    const float r20 = __ldg(Rm + 6), r21 = __ldg(Rm + 7), r22 = __ldg(Rm + 8);
    const float t0  = __ldg(Tv + 0), t1  = __ldg(Tv + 1), t2  = __ldg(Tv + 2);

    // world(d) = d * dir + org ;   dir = R @ (ux, uy, 1) ; org = -R @ T
    const float dirx = r00 * ux + r01 * uy + r02;
    const float diry = r10 * ux + r11 * uy + r12;
    const float dirz = r20 * ux + r21 * uy + r22;
    const float orx  = -(r00 * t0 + r01 * t1 + r02 * t2);
    const float ory  = -(r10 * t0 + r11 * t1 + r12 * t2);
    const float orz  = -(r20 * t0 + r21 * t1 + r22 * t2);

    // grid coord g = 127.5*(world*(256/255) + 1) = 128*world + 127.5
    const float Gdx = 128.0f * dirx, Gdy = 128.0f * diry, Gdz = 128.0f * dirz;
    const float G0x = fmaf(128.0f, orx, 127.5f);
    const float G0y = fmaf(128.0f, ory, 127.5f);
    const float G0z = fmaf(128.0f, orz, 127.5f);

    // ray-box slab cull (conservative; skipped samples contribute exactly 0)
    float dlo = 3.0f, dhi = 9.0f;
    slab_axis(Gdx, G0x, dlo, dhi);
    slab_axis(Gdy, G0y, dlo, dhi);
    slab_axis(Gdz, G0z, dlo, dhi);

    int klo = (int)ceilf((dlo - 3.0f) / kstep - 1e-4f);
    int khi = (int)floorf((dhi - 3.0f) / kstep + 1e-4f);
    klo = max(klo, seg * SEGLEN);
    khi = min(khi, seg * SEGLEN + SEGLEN - 1);

    float t = 1.0f, feat = 0.0f;

    #pragma unroll 4
    for (int k = klo; k <= khi; ++k) {
        const float d  = fmaf((float)k, kstep, 3.0f);
        const float gx = fmaf(d, Gdx, G0x);
        const float gy = fmaf(d, Gdy, G0y);
        const float gz = fmaf(d, Gdz, G0z);

        if (gx >= 0.0f && gx < 255.0f &&
            gy >= 0.0f && gy < 255.0f &&
            gz >= 0.0f && gz < 255.0f) {
            // fast path: all 8 corners in-bounds & valid -> weight sum == 1, dens == 0.1
            const int x0 = (int)gx, y0 = (int)gy, z0 = (int)gz;
            const float fx = gx - (float)x0;
            const float fy = gy - (float)y0;
            const float fz = gz - (float)z0;
            const float* p = vol + (((z0 << 8) + y0) << 8) + x0;
            const float v000 = __ldg(p);         const float v001 = __ldg(p + 1);
            const float v010 = __ldg(p + 256);   const float v011 = __ldg(p + 257);
            const float v100 = __ldg(p + 65536); const float v101 = __ldg(p + 65537);
            const float v110 = __ldg(p + 65792); const float v111 = __ldg(p + 65793);
            const float c00 = fmaf(fx, v001 - v000, v000);
            const float c01 = fmaf(fx, v011 - v010, v010);
            const float c10 = fmaf(fx, v101 - v100, v100);
            const float c11 = fmaf(fx, v111 - v110, v110);
            const float c0  = fmaf(fy, c01 - c00, c00);
            const float c1  = fmaf(fy, c11 - c10, c10);
            const float gray = fmaf(fz, c1 - c0, c0);
            feat = fmaf(0.1f * t, gray, feat);
            t *= 0.9f;
        } else if (gx > -1.0f && gx < 256.0f &&
                   gy > -1.0f && gy < 256.0f &&
                   gz > -1.0f && gz < 256.0f) {
            // fringe path: per-corner validity & clamped indices (reference semantics)
            const float xf = floorf(gx), yf = floorf(gy), zf = floorf(gz);
            const int x0 = (int)xf, y0 = (int)yf, z0 = (int)zf;
            const float fx = gx - xf, fy = gy - yf, fz = gz - zf;
            const float wx[2] = {1.0f - fx, fx};
            const float wy[2] = {1.0f - fy, fy};
            const float wz[2] = {1.0f - fz, fz};
            const int   xc[2] = {min(max(x0, 0), 255), min(max(x0 + 1, 0), 255)};
            const int   yc[2] = {min(max(y0, 0), 255), min(max(y0 + 1, 0), 255)};
            const int   zc[2] = {min(max(z0, 0), 255), min(max(z0 + 1, 0), 255)};
            const float vx[2] = {(x0 >= 0 && x0 <= 255) ? 1.0f : 0.0f,
                                 (x0 + 1 >= 0 && x0 + 1 <= 255) ? 1.0f : 0.0f};
            const float vy[2] = {(y0 >= 0 && y0 <= 255) ? 1.0f : 0.0f,
                                 (y0 + 1 >= 0 && y0 + 1 <= 255) ? 1.0f : 0.0f};
            const float vz[2] = {(z0 >= 0 && z0 <= 255) ? 1.0f : 0.0f,
                                 (z0 + 1 >= 0 && z0 + 1 <= 255) ? 1.0f : 0.0f};
            float gray = 0.0f, ws = 0.0f;
            #pragma unroll
            for (int dz2 = 0; dz2 < 2; ++dz2)
                #pragma unroll
                for (int dy2 = 0; dy2 < 2; ++dy2)
                    #pragma unroll
                    for (int dx2 = 0; dx2 < 2; ++dx2) {
                        const float wv = wx[dx2] * wy[dy2] * wz[dz2]
                                       * vx[dx2] * vy[dy2] * vz[dz2];
                        const float v = __ldg(vol + (((zc[dz2] << 8) + yc[dy2]) << 8) + xc[dx2]);
                        gray = fmaf(wv, v, gray);
                        ws += wv;
                    }
            const float dens = 0.1f * ws;
            feat = fmaf(dens * t, gray, feat);
            t *= (1.0f - dens);
        }
        // fully outside: dens == 0, nothing changes
    }

    const int pix = h * IMG + w;
    g_feat[seg][pix]  = feat;
    g_trans[seg][pix] = t;
}

__global__ void combine_kernel() {
    const int i = blockIdx.x * blockDim.x + threadIdx.x;
    float t = 1.0f, feat = 0.0f;
    #pragma unroll
    for (int s = 0; s < NSEG; ++s) {
        feat = fmaf(t, g_feat[s][i], feat);
        t *= g_trans[s][i];
    }
    const float screen = (3.0f * feat + (1.0f - t)) * 0.25f;
    const int w = i & 255, h = i >> 8;
    g_screen[w * IMG + h] = screen;   // transpose (0,2,1) baked in
}

__global__ void reduce_kernel() {
    __shared__ double s_sum[1024];
    __shared__ double s_sq[1024];
    __shared__ float  s_mn[1024];
    __shared__ float  s_mx[1024];
    const int tid = threadIdx.x;
    double sum = 0.0, sq = 0.0;
    float mn = 1e30f, mx = -1e30f;
    for (int i = tid; i < IMG * IMG; i += 1024) {
        const float v = g_screen[i];
        sum += (double)v;
        sq  += (double)v * (double)v;
        mn = fminf(mn, v);
        mx = fmaxf(mx, v);
    }
    s_sum[tid] = sum; s_sq[tid] = sq; s_mn[tid] = mn; s_mx[tid] = mx;
    __syncthreads();
    for (int o = 512; o > 0; o >>= 1) {
        if (tid < o) {
            s_sum[tid] += s_sum[tid + o];
            s_sq[tid]  += s_sq[tid + o];
            s_mn[tid] = fminf(s_mn[tid], s_mn[tid + o]);
            s_mx[tid] = fmaxf(s_mx[tid], s_mx[tid + o]);
        }
        __syncthreads();
    }
    if (tid == 0) {
        const double n = (double)(IMG * IMG);
        const double mean = s_sum[0] / n;
        const double var  = (s_sq[0] - s_sum[0] * s_sum[0] / n) / (n - 1.0);
        const float stdv = (float)sqrt(var);
        const float inv  = 1.0f / (stdv + 1e-8f);
        const float smin = (s_mn[0] - (float)mean) * inv;
        const float smax = (s_mx[0] - (float)mean) * inv;
        g_consts[0] = (float)mean;
        g_consts[1] = inv;
        g_consts[2] = smin;
        g_consts[3] = 1.0f / (smax - smin + 1e-8f);
    }
}

__global__ void finalize_kernel(float* __restrict__ out) {
    const int i = blockIdx.x * blockDim.x + threadIdx.x;
    const float mean = g_consts[0];
    const float inv  = g_consts[1];
    const float smin = g_consts[2];
    const float invR = g_consts[3];
    const float s = (g_screen[i] - mean) * inv;
    out[i] = (s - smin + 1e-8f) * invR;
}

extern "C" void kernel_launch(void* const* d_in, const int* in_sizes, int n_in,
                              void* d_out, int out_size) {
    const float* vol = (const float*)d_in[0];   // image3d (1,1,256,256,256)
    const float* Rm  = (const float*)d_in[1];   // R (1,3,3)
    const float* Tv  = (const float*)d_in[2];   // T (1,3)
    const float* Fv  = (const float*)d_in[3];   // focal (1,)

    render_kernel<<<dim3(32, 32, NSEG), dim3(8, 8)>>>(vol, Rm, Tv, Fv);
    combine_kernel<<<IMG * IMG / 256, 256>>>();
    reduce_kernel<<<1, 1024>>>();
    finalize_kernel<<<IMG * IMG / 256, 256>>>((float*)d_out);
}

// round 16
// speedup vs baseline: 1.8784x; 1.8784x over previous
#include <cuda_runtime.h>

#define IMG   256
#define NPTS  320
#define NSEG  4
#define SEGLEN (NPTS / NSEG)

// Scratch (device globals: no allocations allowed)
__device__ float  g_feat[NSEG][IMG * IMG];
__device__ float  g_trans[NSEG][IMG * IMG];
__device__ float  g_screen[IMG * IMG];
__device__ double g_psum[256];
__device__ double g_psq[256];
__device__ float  g_pmn[256];
__device__ float  g_pmx[256];

__device__ __forceinline__ void slab_axis(float Gd, float G0, float lo, float hi,
                                          float& dlo, float& dhi) {
    if (fabsf(Gd) > 1e-12f) {
        float inv = 1.0f / Gd;
        float a = (lo - G0) * inv;
        float b = (hi - G0) * inv;
        dlo = fmaxf(dlo, fminf(a, b));
        dhi = fminf(dhi, fmaxf(a, b));
    } else if (G0 <= lo || G0 >= hi) {
        dhi = -1.0f;  // empty
    }
}

// branch-free interior sample: all 8 corners guaranteed in-bounds & valid
__device__ __forceinline__ void sample_fast(const float* __restrict__ vol,
                                            float gx, float gy, float gz,
                                            float& t, float& feat) {
    const int x0 = (int)gx, y0 = (int)gy, z0 = (int)gz;
    const float fx = gx - (float)x0;
    const float fy = gy - (float)y0;
    const float fz = gz - (float)z0;
    const float* p = vol + (((z0 << 8) + y0) << 8) + x0;
    const float v000 = __ldg(p);         const float v001 = __ldg(p + 1);
    const float v010 = __ldg(p + 256);   const float v011 = __ldg(p + 257);
    const float v100 = __ldg(p + 65536); const float v101 = __ldg(p + 65537);
    const float v110 = __ldg(p + 65792); const float v111 = __ldg(p + 65793);
    const float c00 = fmaf(fx, v001 - v000, v000);
    const float c01 = fmaf(fx, v011 - v010, v010);
    const float c10 = fmaf(fx, v101 - v100, v100);
    const float c11 = fmaf(fx, v111 - v110, v110);
    const float c0  = fmaf(fy, c01 - c00, c00);
    const float c1  = fmaf(fy, c11 - c10, c10);
    const float gray = fmaf(fz, c1 - c0, c0);
    feat = fmaf(0.1f * t, gray, feat);
    t *= 0.9f;
}

// full sample with bounds checks + clamped fringe handling (reference semantics)
__device__ __forceinline__ void sample_full(const float* __restrict__ vol,
                                            float gx, float gy, float gz,
                                            float& t, float& feat) {
    if (gx >= 0.0f && gx < 255.0f &&
        gy >= 0.0f && gy < 255.0f &&
        gz >= 0.0f && gz < 255.0f) {
        sample_fast(vol, gx, gy, gz, t, feat);
    } else if (gx > -1.0f && gx < 256.0f &&
               gy > -1.0f && gy < 256.0f &&
               gz > -1.0f && gz < 256.0f) {
        const float xf = floorf(gx), yf = floorf(gy), zf = floorf(gz);
        const int x0 = (int)xf, y0 = (int)yf, z0 = (int)zf;
        const float fx = gx - xf, fy = gy - yf, fz = gz - zf;
        const float wx[2] = {1.0f - fx, fx};
        const float wy[2] = {1.0f - fy, fy};
        const float wz[2] = {1.0f - fz, fz};
        const int   xc[2] = {min(max(x0, 0), 255), min(max(x0 + 1, 0), 255)};
        const int   yc[2] = {min(max(y0, 0), 255), min(max(y0 + 1, 0), 255)};
        const int   zc[2] = {min(max(z0, 0), 255), min(max(z0 + 1, 0), 255)};
        const float vx[2] = {(x0 >= 0 && x0 <= 255) ? 1.0f : 0.0f,
                             (x0 + 1 >= 0 && x0 + 1 <= 255) ? 1.0f : 0.0f};
        const float vy[2] = {(y0 >= 0 && y0 <= 255) ? 1.0f : 0.0f,
                             (y0 + 1 >= 0 && y0 + 1 <= 255) ? 1.0f : 0.0f};
        const float vz[2] = {(z0 >= 0 && z0 <= 255) ? 1.0f : 0.0f,
                             (z0 + 1 >= 0 && z0 + 1 <= 255) ? 1.0f : 0.0f};
        float gray = 0.0f, ws = 0.0f;
        #pragma unroll
        for (int dz2 = 0; dz2 < 2; ++dz2)
            #pragma unroll
            for (int dy2 = 0; dy2 < 2; ++dy2)
                #pragma unroll
                for (int dx2 = 0; dx2 < 2; ++dx2) {
                    const float wv = wx[dx2] * wy[dy2] * wz[dz2]
                                   * vx[dx2] * vy[dy2] * vz[dz2];
                    const float v = __ldg(vol + (((zc[dz2] << 8) + yc[dy2]) << 8) + xc[dx2]);
                    gray = fmaf(wv, v, gray);
                    ws += wv;
                }
        const float dens = 0.1f * ws;
        feat = fmaf(dens * t, gray, feat);
        t *= (1.0f - dens);
    }
    // fully outside: contributes exactly 0
}

__global__ void __launch_bounds__(64) render_kernel(
    const float* __restrict__ vol,
    const float* __restrict__ Rm,
    const float* __restrict__ Tv,
    const float* __restrict__ Fv)
{
    const int w   = blockIdx.x * 8 + threadIdx.x;
    const int h   = blockIdx.y * 8 + threadIdx.y;
    const int seg = blockIdx.z;
    const float kstep = 6.0f / 319.0f;

    const float f  = __ldg(Fv);
    const float ux = (255.0f - 2.0f * (float)w) * (1.0f / 256.0f) / f;
    const float uy = (255.0f - 2.0f * (float)h) * (1.0f / 256.0f) / f;

    const float r00 = __ldg(Rm + 0), r01 = __ldg(Rm + 1), r02 = __ldg(Rm + 2);
    const float r10 = __ldg(Rm + 3), r11 = __ldg(Rm + 4), r12 = __ldg(Rm + 5);
    const float r20 = __ldg(Rm + 6), r21 = __ldg(Rm + 7), r22 = __ldg(Rm + 8);
    const float t0  = __ldg(Tv + 0), t1  = __ldg(Tv + 1), t2  = __ldg(Tv + 2);

    const float dirx = r00 * ux + r01 * uy + r02;
    const float diry = r10 * ux + r11 * uy + r12;
    const float dirz = r20 * ux + r21 * uy + r22;
    const float orx  = -(r00 * t0 + r01 * t1 + r02 * t2);
    const float ory  = -(r10 * t0 + r11 * t1 + r12 * t2);
    const float orz  = -(r20 * t0 + r21 * t1 + r22 * t2);

    const float Gdx = 128.0f * dirx, Gdy = 128.0f * diry, Gdz = 128.0f * dirz;
    const float G0x = fmaf(128.0f, orx, 127.5f);
    const float G0y = fmaf(128.0f, ory, 127.5f);
    const float G0z = fmaf(128.0f, orz, 127.5f);

    // outer slab: any contribution (grid coord in open (-1, 256))
    float dlo = 3.0f, dhi = 9.0f;
    slab_axis(Gdx, G0x, -1.0f, 256.0f, dlo, dhi);
    slab_axis(Gdy, G0y, -1.0f, 256.0f, dlo, dhi);
    slab_axis(Gdz, G0z, -1.0f, 256.0f, dlo, dhi);

    int klo = (int)ceilf((dlo - 3.0f) / kstep - 1e-4f);
    int khi = (int)floorf((dhi - 3.0f) / kstep + 1e-4f);
    klo = max(klo, seg * SEGLEN);
    khi = min(khi, seg * SEGLEN + SEGLEN - 1);

    // inner slab: guaranteed fast path ([margin, 255-margin] on all axes)
    float dloI = 3.0f, dhiI = 9.0f;
    slab_axis(Gdx, G0x, 1e-3f, 254.999f, dloI, dhiI);
    slab_axis(Gdy, G0y, 1e-3f, 254.999f, dloI, dhiI);
    slab_axis(Gdz, G0z, 1e-3f, 254.999f, dloI, dhiI);

    int kloI = (int)ceilf((dloI - 3.0f) / kstep + 1e-4f);
    int khiI = (int)floorf((dhiI - 3.0f) / kstep - 1e-4f);
    kloI = max(kloI, klo);
    khiI = min(khiI, khi);
    if (kloI > khiI) { kloI = khi + 1; khiI = khi; }  // no interior -> all fringe

    float t = 1.0f, feat = 0.0f;

    // fringe head
    for (int k = klo; k <= min(khi, kloI - 1); ++k) {
        const float d = fmaf((float)k, kstep, 3.0f);
        sample_full(vol, fmaf(d, Gdx, G0x), fmaf(d, Gdy, G0y), fmaf(d, Gdz, G0z), t, feat);
    }
    // branch-free interior core
    #pragma unroll 4
    for (int k = kloI; k <= khiI; ++k) {
        const float d = fmaf((float)k, kstep, 3.0f);
        sample_fast(vol, fmaf(d, Gdx, G0x), fmaf(d, Gdy, G0y), fmaf(d, Gdz, G0z), t, feat);
    }
    // fringe tail
    for (int k = khiI + 1; k <= khi; ++k) {
        const float d = fmaf((float)k, kstep, 3.0f);
        sample_full(vol, fmaf(d, Gdx, G0x), fmaf(d, Gdy, G0y), fmaf(d, Gdz, G0z), t, feat);
    }

    const int pix = h * IMG + w;
    g_feat[seg][pix]  = feat;
    g_trans[seg][pix] = t;
}

// combine segments, write transposed screen, emit per-block stats partials
__global__ void combine_stats_kernel() {
    __shared__ double s_sum[256];
    __shared__ double s_sq[256];
    __shared__ float  s_mn[256];
    __shared__ float  s_mx[256];
    const int tid = threadIdx.x;
    const int i = blockIdx.x * 256 + tid;

    float t = 1.0f, feat = 0.0f;
    #pragma unroll
    for (int s = 0; s < NSEG; ++s) {
        feat = fmaf(t, g_feat[s][i], feat);
        t *= g_trans[s][i];
    }
    const float screen = (3.0f * feat + (1.0f - t)) * 0.25f;
    const int w = i & 255, h = i >> 8;
    g_screen[w * IMG + h] = screen;   // transpose (0,2,1) baked in

    s_sum[tid] = (double)screen;
    s_sq[tid]  = (double)screen * (double)screen;
    s_mn[tid]  = screen;
    s_mx[tid]  = screen;
    __syncthreads();
    for (int o = 128; o > 0; o >>= 1) {
        if (tid < o) {
            s_sum[tid] += s_sum[tid + o];
            s_sq[tid]  += s_sq[tid + o];
            s_mn[tid] = fminf(s_mn[tid], s_mn[tid + o]);
            s_mx[tid] = fmaxf(s_mx[tid], s_mx[tid + o]);
        }
        __syncthreads();
    }
    if (tid == 0) {
        g_psum[blockIdx.x] = s_sum[0];
        g_psq[blockIdx.x]  = s_sq[0];
        g_pmn[blockIdx.x]  = s_mn[0];
        g_pmx[blockIdx.x]  = s_mx[0];
    }
}

// every block redundantly reduces the 256 partials, then normalizes its pixels
__global__ void final_kernel(float* __restrict__ out) {
    __shared__ double s_sum[256];
    __shared__ double s_sq[256];
    __shared__ float  s_mn[256];
    __shared__ float  s_mx[256];
    const int tid = threadIdx.x;

    s_sum[tid] = g_psum[tid];
    s_sq[tid]  = g_psq[tid];
    s_mn[tid]  = g_pmn[tid];
    s_mx[tid]  = g_pmx[tid];
    __syncthreads();
    for (int o = 128; o > 0; o >>= 1) {
        if (tid < o) {
            s_sum[tid] += s_sum[tid + o];
            s_sq[tid]  += s_sq[tid + o];
            s_mn[tid] = fminf(s_mn[tid], s_mn[tid + o]);
            s_mx[tid] = fmaxf(s_mx[tid], s_mx[tid + o]);
        }
        __syncthreads();
    }

    const double n    = (double)(IMG * IMG);
    const double mean = s_sum[0] / n;
    const double var  = (s_sq[0] - s_sum[0] * s_sum[0] / n) / (n - 1.0);
    const float stdv  = (float)sqrt(var);
    const float inv   = 1.0f / (stdv + 1e-8f);
    const float smin  = (s_mn[0] - (float)mean) * inv;
    const float smax  = (s_mx[0] - (float)mean) * inv;
    const float invR  = 1.0f / (smax - smin + 1e-8f);

    const int i = blockIdx.x * 256 + tid;
    const float s = (g_screen[i] - (float)mean) * inv;
    out[i] = (s - smin + 1e-8f) * invR;
}

extern "C" void kernel_launch(void* const* d_in, const int* in_sizes, int n_in,
                              void* d_out, int out_size) {
    const float* vol = (const float*)d_in[0];   // image3d (1,1,256,256,256)
    const float* Rm  = (const float*)d_in[1];   // R (1,3,3)
    const float* Tv  = (const float*)d_in[2];   // T (1,3)
    const float* Fv  = (const float*)d_in[3];   // focal (1,)

    render_kernel<<<dim3(32, 32, NSEG), dim3(8, 8)>>>(vol, Rm, Tv, Fv);
    combine_stats_kernel<<<256, 256>>>();
    final_kernel<<<256, 256>>>((float*)d_out);
}